// round 11
// baseline (speedup 1.0000x reference)
#include <cuda_runtime.h>
#include <cuda_bf16.h>
#include <math.h>

#define NG    1024
#define IMG   256
#define TILE  16
#define NTIL  (IMG / TILE)      // 16 -> 256 blocks, ONE kernel
#define HW    (IMG * IMG)
#define NT    256
#define GPT   4
#define MAXP  516               // pair slots: 1024/2 + pad

typedef unsigned long long u64;

// ---- hardware MUFU ----
__device__ __forceinline__ float ex2a(float x) {
    float y; asm("ex2.approx.f32 %0, %1;" : "=f"(y) : "f"(x)); return y;
}
__device__ __forceinline__ float rcpa(float x) {
    float y; asm("rcp.approx.f32 %0, %1;" : "=f"(y) : "f"(x)); return y;
}

// ---- packed f32x2 ----
__device__ __forceinline__ u64 fma2(u64 a, u64 b, u64 c) {
    u64 d; asm("fma.rn.f32x2 %0, %1, %2, %3;" : "=l"(d) : "l"(a), "l"(b), "l"(c)); return d;
}
__device__ __forceinline__ u64 mul2(u64 a, u64 b) {
    u64 d; asm("mul.rn.f32x2 %0, %1, %2;" : "=l"(d) : "l"(a), "l"(b)); return d;
}
__device__ __forceinline__ u64 add2(u64 a, u64 b) {
    u64 d; asm("add.rn.f32x2 %0, %1, %2;" : "=l"(d) : "l"(a), "l"(b)); return d;
}
__device__ __forceinline__ u64 pack2(float lo, float hi) {
    u64 d; asm("mov.b64 %0, {%1, %2};" : "=l"(d) : "f"(lo), "f"(hi)); return d;
}
__device__ __forceinline__ void unpack2(u64 v, float& lo, float& hi) {
    asm("mov.b64 {%0, %1}, %2;" : "=f"(lo), "=f"(hi) : "l"(v));
}

// Pair-interleaved SoA smem: s_A {ncx2,ncy2}, s_B {ka2,kb2}, s_C {kc2,fr2}, s_D {fg2,fb2}
__global__ __launch_bounds__(NT, 2)
void fused_render_kernel(const float* __restrict__ xyz,
                         const float* __restrict__ chol,
                         const float* __restrict__ opac,
                         const float* __restrict__ feat,
                         float* __restrict__ out)
{
    __shared__ __align__(16) float4 s_A[MAXP];
    __shared__ __align__(16) float4 s_B[MAXP];
    __shared__ __align__(16) float4 s_C[MAXP];
    __shared__ __align__(16) float4 s_D[MAXP];
    __shared__ int s_warpcnt[NT / 32];

    const int tid  = threadIdx.x;
    const int warp = tid >> 5;
    const int lane = tid & 31;

    const float x0  = (float)(blockIdx.x * TILE);
    const float y0  = (float)(blockIdx.y * TILE);
    const float xlo = x0 + 0.5f, xhi = x0 + (float)TILE - 0.5f;
    const float ylo = y0 + 0.5f, yhi = y0 + (float)TILE - 0.5f;

    // ---- front loads: ONLY what the cull needs (5 LDG.128 per thread) ----
    const float4* xyz4 = (const float4*)xyz;
    const float4* ch4  = (const float4*)chol;

    float4 xyA = xyz4[tid * 2 + 0];
    float4 xyB = xyz4[tid * 2 + 1];
    float4 chA = ch4[tid * 3 + 0];
    float4 chB = ch4[tid * 3 + 1];
    float4 chC = ch4[tid * 3 + 2];

    float xyv[8]  = {xyA.x, xyA.y, xyA.z, xyA.w, xyB.x, xyB.y, xyB.z, xyB.w};
    float chv[12] = {chA.x, chA.y, chA.z, chA.w, chB.x, chB.y, chB.z, chB.w,
                     chC.x, chC.y, chC.z, chC.w};

    // ---- prep + AABB cull: 2 EX2 + 1 RCP per gaussian ----
    const float K2L2E = 2.8853900817779268f;   // 2*log2(e)
    const float T2    = 25.0f;                 // 2*T, T = 12.5 nats
    float cxv[GPT], cyv[GPT], l1v[GPT], l2v[GPT], av[GPT], cv[GPT];
    bool  hitv[GPT];

    #pragma unroll
    for (int j = 0; j < GPT; j++) {
        float ux = ex2a(xyv[2 * j + 0] * K2L2E);
        float uy = ex2a(xyv[2 * j + 1] * K2L2E);
        float sx = ux + 1.0f, sy = uy + 1.0f;
        float r  = rcpa(sx * sy);                       // one RCP, both axes
        float cx = fmaf(sy * r, -256.0f, 256.0f);       // 256 - 256/sx
        float cy = fmaf(sx * r, -256.0f, 256.0f);       // 256 - 256/sy

        float l1 = chv[3 * j + 0] + 0.5f;
        float l2 = chv[3 * j + 1];
        float l3 = chv[3 * j + 2] + 0.5f;

        float a  = l1 * l1;                 // Sigma_xx
        float cc = fmaf(l2, l2, l3 * l3);   // Sigma_yy  (b deferred to hit branch)

        float dxc = fminf(fmaxf(cx, xlo), xhi) - cx;
        float dyc = fminf(fmaxf(cy, ylo), yhi) - cy;
        bool hit = (dxc * dxc <= T2 * a) && (dyc * dyc <= T2 * cc);

        cxv[j] = cx; cyv[j] = cy; l1v[j] = l1; l2v[j] = l2;
        av[j] = a;  cv[j] = cc;
        hitv[j] = hit;
    }

    // ---- ballot compaction (deterministic (warp,j,lane) order) ----
    unsigned mj[GPT];
    int wc = 0;
    #pragma unroll
    for (int j = 0; j < GPT; j++) {
        mj[j] = __ballot_sync(0xffffffffu, hitv[j]);
        wc += __popc(mj[j]);
    }
    if (lane == 0) s_warpcnt[warp] = wc;
    __syncthreads();

    int wbase = 0, count = 0;
    #pragma unroll
    for (int w = 0; w < NT / 32; w++) {
        int v = s_warpcnt[w];
        if (w < warp) wbase += v;
        count += v;
    }

    float* sAf = (float*)s_A;
    float* sBf = (float*)s_B;
    float* sCf = (float*)s_C;
    float* sDf = (float*)s_D;

    const float L2E = 1.4426950408889634f;
    const unsigned lt = (1u << lane) - 1u;
    {
        int jbase = wbase;
        #pragma unroll
        for (int j = 0; j < GPT; j++) {
            if (hitv[j]) {
                int g   = tid * GPT + j;                  // global gaussian id
                int off = jbase + __popc(mj[j] & lt);
                float b   = l1v[j] * l2v[j];              // Sigma_xy (deferred)
                float inv = rcpa(fmaf(av[j], cv[j], -(b * b)));
                float o   = opac[g];                      // deferred loads (L2 hit)
                float fr  = feat[3 * g + 0];
                float fg  = feat[3 * g + 1];
                float fb  = feat[3 * g + 2];
                int p = off >> 1, h = off & 1, base = 4 * p + h;
                sAf[base]     = -cxv[j];
                sAf[base + 2] = -cyv[j];
                sBf[base]     = -0.5f * L2E * cv[j] * inv;
                sBf[base + 2] =  L2E * b * inv;
                sCf[base]     = -0.5f * L2E * av[j] * inv;
                sCf[base + 2] = fr * o;
                sDf[base]     = fg * o;
                sDf[base + 2] = fb * o;
            }
            jbase += __popc(mj[j]);
        }
    }
    if (tid < 2) {   // NaN-safe pad for odd pair tail (distributed, not serial)
        int k = count + tid;
        int p = k >> 1, h = k & 1, base = 4 * p + h;
        sAf[base] = 0.0f; sAf[base + 2] = 0.0f;
        sBf[base] = 0.0f; sBf[base + 2] = 0.0f;
        sCf[base] = 0.0f; sCf[base + 2] = 0.0f;
        sDf[base] = 0.0f; sDf[base + 2] = 0.0f;
    }
    __syncthreads();

    // ---- packed f32x2 splat: one pixel per thread, 2 gaussians/iter ----
    const int   pxi = blockIdx.x * TILE + (tid & (TILE - 1));
    const int   pyi = blockIdx.y * TILE + (tid >> 4);
    const float px  = (float)pxi + 0.5f;
    const float py  = (float)pyi + 0.5f;

    const u64 px2 = pack2(px, px);
    const u64 py2 = pack2(py, py);
    u64 accr2 = 0ull, accg2 = 0ull, accb2 = 0ull;

    const ulonglong2* pA = (const ulonglong2*)s_A;
    const ulonglong2* pB = (const ulonglong2*)s_B;
    const ulonglong2* pC = (const ulonglong2*)s_C;
    const ulonglong2* pD = (const ulonglong2*)s_D;

    const int pairs = (count + 1) >> 1;
    #pragma unroll 2
    for (int i = 0; i < pairs; i++) {
        ulonglong2 A = pA[i];                  // LDS.128 broadcast
        ulonglong2 B = pB[i];
        ulonglong2 C = pC[i];
        ulonglong2 D = pD[i];
        u64 dx2 = add2(px2, A.x);
        u64 dy2 = add2(py2, A.y);
        u64 u   = fma2(B.y, dy2, mul2(B.x, dx2));          // ka*dx + kb*dy
        u64 t2  = fma2(dx2, u, mul2(mul2(C.x, dy2), dy2)); // + kc*dy^2
        float tl, th; unpack2(t2, tl, th);
        u64 w2  = pack2(ex2a(tl), ex2a(th));               // MUFU.EX2
        accr2 = fma2(w2, C.y, accr2);
        accg2 = fma2(w2, D.x, accg2);
        accb2 = fma2(w2, D.y, accb2);
    }

    float rl, rh, gl, gh, bl, bh;
    unpack2(accr2, rl, rh); unpack2(accg2, gl, gh); unpack2(accb2, bl, bh);
    float accr = fminf(fmaxf(rl + rh, 0.0f), 1.0f);
    float accg = fminf(fmaxf(gl + gh, 0.0f), 1.0f);
    float accb = fminf(fmaxf(bl + bh, 0.0f), 1.0f);

    const int p = pyi * IMG + pxi;
    out[0 * HW + p] = accr;
    out[1 * HW + p] = accg;
    out[2 * HW + p] = accb;
}

extern "C" void kernel_launch(void* const* d_in, const int* in_sizes, int n_in,
                              void* d_out, int out_size)
{
    const float* xyz  = (const float*)d_in[0];   // (N,2)
    const float* chol = (const float*)d_in[1];   // (N,3)
    const float* opac = (const float*)d_in[2];   // (N,1)
    const float* feat = (const float*)d_in[3];   // (N,3)
    float* out = (float*)d_out;                  // (1,3,256,256)

    dim3 grid(NTIL, NTIL);                       // 16x16 = 256 blocks, ONE kernel
    fused_render_kernel<<<grid, NT>>>(xyz, chol, opac, feat, out);
}

// round 12
// speedup vs baseline: 1.2917x; 1.2917x over previous
#include <cuda_runtime.h>
#include <cuda_bf16.h>
#include <math.h>

#define NG    1024
#define IMG   256
#define TILE  16
#define NTIL  (IMG / TILE)      // 16 -> 256 blocks, ONE kernel
#define HW    (IMG * IMG)
#define NT    256
#define GPT   4
#define MAXP  516               // pair slots: 1024/2 + pad

typedef unsigned long long u64;

// ---- hardware MUFU ----
__device__ __forceinline__ float ex2a(float x) {
    float y; asm("ex2.approx.f32 %0, %1;" : "=f"(y) : "f"(x)); return y;
}
__device__ __forceinline__ float rcpa(float x) {
    float y; asm("rcp.approx.f32 %0, %1;" : "=f"(y) : "f"(x)); return y;
}

// ---- packed f32x2 ----
__device__ __forceinline__ u64 fma2(u64 a, u64 b, u64 c) {
    u64 d; asm("fma.rn.f32x2 %0, %1, %2, %3;" : "=l"(d) : "l"(a), "l"(b), "l"(c)); return d;
}
__device__ __forceinline__ u64 mul2(u64 a, u64 b) {
    u64 d; asm("mul.rn.f32x2 %0, %1, %2;" : "=l"(d) : "l"(a), "l"(b)); return d;
}
__device__ __forceinline__ u64 add2(u64 a, u64 b) {
    u64 d; asm("add.rn.f32x2 %0, %1, %2;" : "=l"(d) : "l"(a), "l"(b)); return d;
}
__device__ __forceinline__ u64 pack2(float lo, float hi) {
    u64 d; asm("mov.b64 %0, {%1, %2};" : "=l"(d) : "f"(lo), "f"(hi)); return d;
}
__device__ __forceinline__ void unpack2(u64 v, float& lo, float& hi) {
    asm("mov.b64 {%0, %1}, %2;" : "=f"(lo), "=f"(hi) : "l"(v));
}

// Pair-interleaved SoA smem: s_A {ncx2,ncy2}, s_B {ka2,kb2}, s_C {kc2,fr2}, s_D {fg2,fb2}
__global__ __launch_bounds__(NT, 2)
void fused_render_kernel(const float* __restrict__ xyz,
                         const float* __restrict__ chol,
                         const float* __restrict__ opac,
                         const float* __restrict__ feat,
                         float* __restrict__ out)
{
    __shared__ __align__(16) float4 s_A[MAXP];
    __shared__ __align__(16) float4 s_B[MAXP];
    __shared__ __align__(16) float4 s_C[MAXP];
    __shared__ __align__(16) float4 s_D[MAXP];
    __shared__ int s_warpcnt[NT / 32];

    const int tid  = threadIdx.x;
    const int warp = tid >> 5;
    const int lane = tid & 31;

    const float x0  = (float)(blockIdx.x * TILE);
    const float y0  = (float)(blockIdx.y * TILE);
    const float xlo = x0 + 0.5f, xhi = x0 + (float)TILE - 0.5f;
    const float ylo = y0 + 0.5f, yhi = y0 + (float)TILE - 0.5f;

    // ---- front-batched loads: ALL inputs, one overlapped latency exposure ----
    const float4* xyz4 = (const float4*)xyz;
    const float4* ch4  = (const float4*)chol;
    const float4* op4  = (const float4*)opac;
    const float4* ft4  = (const float4*)feat;

    float4 xyA = xyz4[tid * 2 + 0];
    float4 xyB = xyz4[tid * 2 + 1];
    float4 chA = ch4[tid * 3 + 0];
    float4 chB = ch4[tid * 3 + 1];
    float4 chC = ch4[tid * 3 + 2];
    float4 opV = op4[tid];
    float4 ftA = ft4[tid * 3 + 0];
    float4 ftB = ft4[tid * 3 + 1];
    float4 ftC = ft4[tid * 3 + 2];

    float xyv[8]  = {xyA.x, xyA.y, xyA.z, xyA.w, xyB.x, xyB.y, xyB.z, xyB.w};
    float chv[12] = {chA.x, chA.y, chA.z, chA.w, chB.x, chB.y, chB.z, chB.w,
                     chC.x, chC.y, chC.z, chC.w};
    float ftv[12] = {ftA.x, ftA.y, ftA.z, ftA.w, ftB.x, ftB.y, ftB.z, ftB.w,
                     ftC.x, ftC.y, ftC.z, ftC.w};
    float opv[4]  = {opV.x, opV.y, opV.z, opV.w};

    // ---- prep + AABB cull: 2 EX2 + 1 RCP per gaussian ----
    const float K2L2E = 2.8853900817779268f;   // 2*log2(e)
    const float T2    = 25.0f;                 // 2*T, T = 12.5 nats
    float cxv[GPT], cyv[GPT], l1v[GPT], l2v[GPT], av[GPT], cv[GPT];
    bool  hitv[GPT];

    #pragma unroll
    for (int j = 0; j < GPT; j++) {
        float ux = ex2a(xyv[2 * j + 0] * K2L2E);
        float uy = ex2a(xyv[2 * j + 1] * K2L2E);
        float sx = ux + 1.0f, sy = uy + 1.0f;
        float r  = rcpa(sx * sy);                       // one RCP, both axes
        float cx = fmaf(sy * r, -256.0f, 256.0f);       // 256 - 256/sx
        float cy = fmaf(sx * r, -256.0f, 256.0f);       // 256 - 256/sy

        float l1 = chv[3 * j + 0] + 0.5f;
        float l2 = chv[3 * j + 1];
        float l3 = chv[3 * j + 2] + 0.5f;

        float a  = l1 * l1;                 // Sigma_xx
        float cc = fmaf(l2, l2, l3 * l3);   // Sigma_yy   (b deferred: compute only)

        float dxc = fminf(fmaxf(cx, xlo), xhi) - cx;
        float dyc = fminf(fmaxf(cy, ylo), yhi) - cy;
        bool hit = (dxc * dxc <= T2 * a) && (dyc * dyc <= T2 * cc);

        cxv[j] = cx; cyv[j] = cy; l1v[j] = l1; l2v[j] = l2;
        av[j] = a;  cv[j] = cc;
        hitv[j] = hit;
    }

    // ---- ballot compaction (deterministic (warp,j,lane) order) ----
    unsigned mj[GPT];
    int wc = 0;
    #pragma unroll
    for (int j = 0; j < GPT; j++) {
        mj[j] = __ballot_sync(0xffffffffu, hitv[j]);
        wc += __popc(mj[j]);
    }
    if (lane == 0) s_warpcnt[warp] = wc;
    __syncthreads();

    int wbase = 0, count = 0;
    #pragma unroll
    for (int w = 0; w < NT / 32; w++) {
        int v = s_warpcnt[w];
        if (w < warp) wbase += v;
        count += v;
    }

    float* sAf = (float*)s_A;
    float* sBf = (float*)s_B;
    float* sCf = (float*)s_C;
    float* sDf = (float*)s_D;

    const float L2E = 1.4426950408889634f;
    const unsigned lt = (1u << lane) - 1u;
    {
        int jbase = wbase;
        #pragma unroll
        for (int j = 0; j < GPT; j++) {
            if (hitv[j]) {
                int off = jbase + __popc(mj[j] & lt);
                float b   = l1v[j] * l2v[j];              // Sigma_xy (compute-deferred)
                float inv = rcpa(fmaf(av[j], cv[j], -(b * b)));
                float o   = opv[j];                       // already in registers
                int p = off >> 1, h = off & 1, base = 4 * p + h;
                sAf[base]     = -cxv[j];
                sAf[base + 2] = -cyv[j];
                sBf[base]     = -0.5f * L2E * cv[j] * inv;
                sBf[base + 2] =  L2E * b * inv;
                sCf[base]     = -0.5f * L2E * av[j] * inv;
                sCf[base + 2] = ftv[3 * j + 0] * o;
                sDf[base]     = ftv[3 * j + 1] * o;
                sDf[base + 2] = ftv[3 * j + 2] * o;
            }
            jbase += __popc(mj[j]);
        }
    }
    if (tid < 2) {   // NaN-safe pad for odd pair tail (distributed)
        int k = count + tid;
        int p = k >> 1, h = k & 1, base = 4 * p + h;
        sAf[base] = 0.0f; sAf[base + 2] = 0.0f;
        sBf[base] = 0.0f; sBf[base + 2] = 0.0f;
        sCf[base] = 0.0f; sCf[base + 2] = 0.0f;
        sDf[base] = 0.0f; sDf[base + 2] = 0.0f;
    }
    __syncthreads();

    // ---- packed f32x2 splat: one pixel per thread, 2 gaussians/iter ----
    const int   pxi = blockIdx.x * TILE + (tid & (TILE - 1));
    const int   pyi = blockIdx.y * TILE + (tid >> 4);
    const float px  = (float)pxi + 0.5f;
    const float py  = (float)pyi + 0.5f;

    const u64 px2 = pack2(px, px);
    const u64 py2 = pack2(py, py);
    u64 accr2 = 0ull, accg2 = 0ull, accb2 = 0ull;

    const ulonglong2* pA = (const ulonglong2*)s_A;
    const ulonglong2* pB = (const ulonglong2*)s_B;
    const ulonglong2* pC = (const ulonglong2*)s_C;
    const ulonglong2* pD = (const ulonglong2*)s_D;

    const int pairs = (count + 1) >> 1;
    #pragma unroll 2
    for (int i = 0; i < pairs; i++) {
        ulonglong2 A = pA[i];                  // LDS.128 broadcast
        ulonglong2 B = pB[i];
        ulonglong2 C = pC[i];
        ulonglong2 D = pD[i];
        u64 dx2 = add2(px2, A.x);
        u64 dy2 = add2(py2, A.y);
        u64 u   = fma2(B.y, dy2, mul2(B.x, dx2));          // ka*dx + kb*dy
        u64 t2  = fma2(dx2, u, mul2(mul2(C.x, dy2), dy2)); // + kc*dy^2
        float tl, th; unpack2(t2, tl, th);
        u64 w2  = pack2(ex2a(tl), ex2a(th));               // MUFU.EX2
        accr2 = fma2(w2, C.y, accr2);
        accg2 = fma2(w2, D.x, accg2);
        accb2 = fma2(w2, D.y, accb2);
    }

    float rl, rh, gl, gh, bl, bh;
    unpack2(accr2, rl, rh); unpack2(accg2, gl, gh); unpack2(accb2, bl, bh);
    float accr = fminf(fmaxf(rl + rh, 0.0f), 1.0f);
    float accg = fminf(fmaxf(gl + gh, 0.0f), 1.0f);
    float accb = fminf(fmaxf(bl + bh, 0.0f), 1.0f);

    const int p = pyi * IMG + pxi;
    out[0 * HW + p] = accr;
    out[1 * HW + p] = accg;
    out[2 * HW + p] = accb;
}

extern "C" void kernel_launch(void* const* d_in, const int* in_sizes, int n_in,
                              void* d_out, int out_size)
{
    const float* xyz  = (const float*)d_in[0];   // (N,2)
    const float* chol = (const float*)d_in[1];   // (N,3)
    const float* opac = (const float*)d_in[2];   // (N,1)
    const float* feat = (const float*)d_in[3];   // (N,3)
    float* out = (float*)d_out;                  // (1,3,256,256)

    dim3 grid(NTIL, NTIL);                       // 16x16 = 256 blocks, ONE kernel
    fused_render_kernel<<<grid, NT>>>(xyz, chol, opac, feat, out);
}

// round 13
// speedup vs baseline: 1.3223x; 1.0237x over previous
#include <cuda_runtime.h>
#include <cuda_bf16.h>
#include <math.h>

#define NG    1024
#define IMG   256
#define TILE  16
#define NTIL  (IMG / TILE)      // 16 -> 256 blocks, ONE kernel
#define HW    (IMG * IMG)
#define NT    256
#define GPT   4
#define MAXP  516               // pair slots (capacity 1032 gaussian slots)

typedef unsigned long long u64;

// ---- hardware MUFU ----
__device__ __forceinline__ float ex2a(float x) {
    float y; asm("ex2.approx.f32 %0, %1;" : "=f"(y) : "f"(x)); return y;
}
__device__ __forceinline__ float rcpa(float x) {
    float y; asm("rcp.approx.f32 %0, %1;" : "=f"(y) : "f"(x)); return y;
}
__device__ __forceinline__ float lg2a(float x) {
    float y; asm("lg2.approx.f32 %0, %1;" : "=f"(y) : "f"(x)); return y;
}

// ---- packed f32x2 ----
__device__ __forceinline__ u64 fma2(u64 a, u64 b, u64 c) {
    u64 d; asm("fma.rn.f32x2 %0, %1, %2, %3;" : "=l"(d) : "l"(a), "l"(b), "l"(c)); return d;
}
__device__ __forceinline__ u64 mul2(u64 a, u64 b) {
    u64 d; asm("mul.rn.f32x2 %0, %1, %2;" : "=l"(d) : "l"(a), "l"(b)); return d;
}
__device__ __forceinline__ u64 add2(u64 a, u64 b) {
    u64 d; asm("add.rn.f32x2 %0, %1, %2;" : "=l"(d) : "l"(a), "l"(b)); return d;
}
__device__ __forceinline__ u64 pack2(float lo, float hi) {
    u64 d; asm("mov.b64 %0, {%1, %2};" : "=l"(d) : "f"(lo), "f"(hi)); return d;
}
__device__ __forceinline__ void unpack2(u64 v, float& lo, float& hi) {
    asm("mov.b64 {%0, %1}, %2;" : "=f"(lo), "=f"(hi) : "l"(v));
}

// atanh with saturation: conservative window bound in raw-x space.
__device__ __forceinline__ float atanh_lo(float u) {
    if (u <= -0.999f) return -1e30f;
    if (u >=  0.999f) return  1e30f;
    return 0.34657359f * lg2a((1.0f + u) * rcpa(1.0f - u));   // 0.5*ln2
}

__global__ __launch_bounds__(NT, 2)
void fused_render_kernel(const float* __restrict__ xyz,
                         const float* __restrict__ chol,
                         const float* __restrict__ opac,
                         const float* __restrict__ feat,
                         float* __restrict__ out)
{
    __shared__ __align__(16) float4 s_A[MAXP];   // {ncx2, ncy2}
    __shared__ __align__(16) float4 s_B[MAXP];   // {ka2,  kb2}
    __shared__ __align__(16) float4 s_C[MAXP];   // {kc2,  fr2}
    __shared__ __align__(16) float4 s_D[MAXP];   // {fg2,  fb2}
    __shared__ short s_sidx[NG];
    __shared__ int   s_warpcnt[NT / 32];

    const int tid  = threadIdx.x;
    const int warp = tid >> 5;
    const int lane = tid & 31;

    const float x0  = (float)(blockIdx.x * TILE);
    const float y0  = (float)(blockIdx.y * TILE);

    // Raw-input-space window (computed redundantly by all threads; ~8 MUFU total).
    // Margin 10.5 px >= wx_max(7.5), wy_max(9.0) for this problem's Sigma bounds,
    // plus approx slack. Pixel->x map: px = 128*(tanh(x)+1), monotone.
    const float M = 10.5f;
    const float Xlo = atanh_lo((x0 + 0.5f  - M) * 0.0078125f - 1.0f);
    const float Xhi = atanh_lo((x0 + 15.5f + M) * 0.0078125f - 1.0f);
    const float Ylo = atanh_lo((y0 + 0.5f  - M) * 0.0078125f - 1.0f);
    const float Yhi = atanh_lo((y0 + 15.5f + M) * 0.0078125f - 1.0f);

    // ---- phase 1: xyz-only coarse cull (2 LDG.128, pure compares) ----
    const float4* xyz4 = (const float4*)xyz;
    float4 xyA = xyz4[tid * 2 + 0];          // gaussians 4t, 4t+1
    float4 xyB = xyz4[tid * 2 + 1];          // gaussians 4t+2, 4t+3
    float xyv[8] = {xyA.x, xyA.y, xyA.z, xyA.w, xyB.x, xyB.y, xyB.z, xyB.w};

    bool hitv[GPT];
    #pragma unroll
    for (int j = 0; j < GPT; j++) {
        float x = xyv[2 * j + 0];
        float y = xyv[2 * j + 1];
        hitv[j] = (x >= Xlo) & (x <= Xhi) & (y >= Ylo) & (y <= Yhi);
    }

    unsigned mj[GPT];
    int wc = 0;
    #pragma unroll
    for (int j = 0; j < GPT; j++) {
        mj[j] = __ballot_sync(0xffffffffu, hitv[j]);
        wc += __popc(mj[j]);
    }
    if (lane == 0) s_warpcnt[warp] = wc;
    __syncthreads();                                      // B1

    int wbase = 0, nsurv = 0;
    #pragma unroll
    for (int w = 0; w < NT / 32; w++) {
        int v = s_warpcnt[w];
        if (w < warp) wbase += v;
        nsurv += v;
    }

    const unsigned lt = (1u << lane) - 1u;
    {
        int jbase = wbase;
        #pragma unroll
        for (int j = 0; j < GPT; j++) {
            if (hitv[j])
                s_sidx[jbase + __popc(mj[j] & lt)] = (short)(tid * GPT + j);
            jbase += __popc(mj[j]);
        }
    }
    __syncthreads();                                      // B2

    // ---- phase 2: prep ONLY survivors (~10-30), write splat slots directly ----
    float* sAf = (float*)s_A;
    float* sBf = (float*)s_B;
    float* sCf = (float*)s_C;
    float* sDf = (float*)s_D;

    const float K2L2E = 2.8853900817779268f;   // 2*log2(e)
    const float L2E   = 1.4426950408889634f;

    for (int s = tid; s < nsurv; s += NT) {
        int g = s_sidx[s];
        float2 xy = ((const float2*)xyz)[g];
        float ux = ex2a(xy.x * K2L2E);
        float uy = ex2a(xy.y * K2L2E);
        float cx = fmaf(rcpa(ux + 1.0f), -256.0f, 256.0f);   // 128*(tanh+1)
        float cy = fmaf(rcpa(uy + 1.0f), -256.0f, 256.0f);

        float l1 = chol[3 * g + 0] + 0.5f;
        float l2 = chol[3 * g + 1];
        float l3 = chol[3 * g + 2] + 0.5f;
        float a  = l1 * l1;
        float b  = l1 * l2;
        float cc = fmaf(l2, l2, l3 * l3);
        float inv = rcpa(fmaf(a, cc, -(b * b)));

        float o  = opac[g];
        float fr = feat[3 * g + 0];
        float fg = feat[3 * g + 1];
        float fb = feat[3 * g + 2];

        int p = s >> 1, h = s & 1, base = 4 * p + h;
        sAf[base]     = -cx;
        sAf[base + 2] = -cy;
        sBf[base]     = -0.5f * L2E * cc * inv;
        sBf[base + 2] =  L2E * b * inv;
        sCf[base]     = -0.5f * L2E * a * inv;
        sCf[base + 2] = fr * o;
        sDf[base]     = fg * o;
        sDf[base + 2] = fb * o;
    }
    if (tid < 2) {   // NaN-safe pad for odd pair tail
        int k = nsurv + tid;
        int p = k >> 1, h = k & 1, base = 4 * p + h;
        sAf[base] = 0.0f; sAf[base + 2] = 0.0f;
        sBf[base] = 0.0f; sBf[base + 2] = 0.0f;
        sCf[base] = 0.0f; sCf[base + 2] = 0.0f;
        sDf[base] = 0.0f; sDf[base + 2] = 0.0f;
    }
    __syncthreads();                                      // B3

    // ---- packed f32x2 splat: one pixel per thread, 2 gaussians/iter ----
    const int   pxi = blockIdx.x * TILE + (tid & (TILE - 1));
    const int   pyi = blockIdx.y * TILE + (tid >> 4);
    const float px  = (float)pxi + 0.5f;
    const float py  = (float)pyi + 0.5f;

    const u64 px2 = pack2(px, px);
    const u64 py2 = pack2(py, py);
    u64 accr2 = 0ull, accg2 = 0ull, accb2 = 0ull;

    const ulonglong2* pA = (const ulonglong2*)s_A;
    const ulonglong2* pB = (const ulonglong2*)s_B;
    const ulonglong2* pC = (const ulonglong2*)s_C;
    const ulonglong2* pD = (const ulonglong2*)s_D;

    const int pairs = (nsurv + 1) >> 1;
    #pragma unroll 2
    for (int i = 0; i < pairs; i++) {
        ulonglong2 A = pA[i];                  // LDS.128 broadcast
        ulonglong2 B = pB[i];
        ulonglong2 C = pC[i];
        ulonglong2 D = pD[i];
        u64 dx2 = add2(px2, A.x);
        u64 dy2 = add2(py2, A.y);
        u64 u   = fma2(B.y, dy2, mul2(B.x, dx2));          // ka*dx + kb*dy
        u64 t2  = fma2(dx2, u, mul2(mul2(C.x, dy2), dy2)); // + kc*dy^2
        float tl, th; unpack2(t2, tl, th);
        u64 w2  = pack2(ex2a(tl), ex2a(th));               // MUFU.EX2
        accr2 = fma2(w2, C.y, accr2);
        accg2 = fma2(w2, D.x, accg2);
        accb2 = fma2(w2, D.y, accb2);
    }

    float rl, rh, gl, gh, bl, bh;
    unpack2(accr2, rl, rh); unpack2(accg2, gl, gh); unpack2(accb2, bl, bh);
    float accr = fminf(fmaxf(rl + rh, 0.0f), 1.0f);
    float accg = fminf(fmaxf(gl + gh, 0.0f), 1.0f);
    float accb = fminf(fmaxf(bl + bh, 0.0f), 1.0f);

    const int p = pyi * IMG + pxi;
    out[0 * HW + p] = accr;
    out[1 * HW + p] = accg;
    out[2 * HW + p] = accb;
}

extern "C" void kernel_launch(void* const* d_in, const int* in_sizes, int n_in,
                              void* d_out, int out_size)
{
    const float* xyz  = (const float*)d_in[0];   // (N,2)
    const float* chol = (const float*)d_in[1];   // (N,3)
    const float* opac = (const float*)d_in[2];   // (N,1)
    const float* feat = (const float*)d_in[3];   // (N,3)
    float* out = (float*)d_out;                  // (1,3,256,256)

    dim3 grid(NTIL, NTIL);                       // 16x16 = 256 blocks, ONE kernel
    fused_render_kernel<<<grid, NT>>>(xyz, chol, opac, feat, out);
}